// round 11
// baseline (speedup 1.0000x reference)
#include <cuda_runtime.h>
#include <cuda_fp16.h>
#include <cstdint>

#define BATCH 8
#define NPTS  2048
#define CIN   64
#define NIP   256            // H width: [c(64) | e(192)]
#define MT    64             // a-rows per CTA == chunk size
#define KC    64             // b's per chunk
#define NCHUNK (NPTS / KC)   // 32
#define THREADS 256

// Static device scratch (allocation is forbidden)
__device__ int    g_key[BATCH][NPTS];
__device__ int    g_hist[BATCH][512];
__device__ int    g_offs[BATCH][512];
__device__ int    g_perm[BATCH][NPTS];
__device__ float4 g_geoms[BATCH][NPTS];       // sorted geometry
__device__ float4 g_bbox[BATCH][NCHUNK][2];   // [lo, hi] per chunk
__device__ __align__(128) __half g_H[(size_t)BATCH * NIP * NPTS];  // sorted cols

// ---- main-kernel smem layout (bytes) ----
#define GEOM_OFF 0u                  // 2048 x float4 = 32768
#define A_OFF    32768u              // 2 x 8192 (64 rows x 128B, SW128)
#define A_STG    8192u
#define B_OFF    49152u              // 2 x 32768 (256 rows x 128B, SW128)
#define B_STG    32768u
#define LIST_OFF 114688u             // 33 ints: active list + count
#define SMEM_MAIN (LIST_OFF + 256u)  // 114944 -> 2 CTAs/SM

// ---- prep-kernel smem (floats) ----
#define PWK_F   0
#define PE_F    12288                // E tile 192 x 72
#define PGB_F   26112                // 64 x float4
#define SMEM_PREP ((26112 + 256) * 4)

__device__ __forceinline__ uint32_t smem_u32(const void* p) {
    uint32_t a;
    asm("{ .reg .u64 t; cvta.to.shared.u64 t, %1; cvt.u32.u64 %0, t; }" : "=r"(a) : "l"(p));
    return a;
}
__device__ __forceinline__ void cpasync16(uint32_t dst, const void* src) {
    asm volatile("cp.async.cg.shared.global [%0], [%1], 16;" :: "r"(dst), "l"(src) : "memory");
}
__device__ __forceinline__ void sts32(uint32_t a, uint32_t v) {
    asm volatile("st.shared.b32 [%0], %1;" :: "r"(a), "r"(v) : "memory");
}
__device__ __forceinline__ void ldsm_x4(uint32_t& r0, uint32_t& r1, uint32_t& r2, uint32_t& r3,
                                        uint32_t addr) {
    asm volatile("ldmatrix.sync.aligned.m8n8.x4.shared.b16 {%0,%1,%2,%3}, [%4];"
                 : "=r"(r0), "=r"(r1), "=r"(r2), "=r"(r3) : "r"(addr));
}
__device__ __forceinline__ void mma16816(float& d0, float& d1, float& d2, float& d3,
                                         uint32_t a0, uint32_t a1, uint32_t a2, uint32_t a3,
                                         uint32_t b0, uint32_t b1) {
    asm volatile(
        "mma.sync.aligned.m16n8k16.row.col.f32.f16.f16.f32 "
        "{%0,%1,%2,%3}, {%4,%5,%6,%7}, {%8,%9}, {%0,%1,%2,%3};"
        : "+f"(d0), "+f"(d1), "+f"(d2), "+f"(d3)
        : "r"(a0), "r"(a1), "r"(a2), "r"(a3), "r"(b0), "r"(b1));
}

// ---------------------------------------------------------------------------
// Sort pipeline (deterministic): Morton-9 cell key -> hist -> scan ->
// sequential per-key scatter -> per-chunk bboxes.
// ---------------------------------------------------------------------------
__global__ __launch_bounds__(512) void key_hist_kernel(const float* __restrict__ geom) {
    __shared__ int sh[512];
    const int z = blockIdx.x, t = threadIdx.x;
    sh[t] = 0;
    __syncthreads();
    for (int i = t; i < NPTS; i += 512) {
        const float* gp = geom + ((size_t)z * NPTS + i) * 3;
        const int kx = min(7, max(0, (int)floorf(gp[0] + 4.0f)));
        const int ky = min(7, max(0, (int)floorf(gp[1] + 4.0f)));
        const int kz = min(7, max(0, (int)floorf(gp[2] + 4.0f)));
        int m = 0;
#pragma unroll
        for (int b = 0; b < 3; b++)
            m |= (((kx >> b) & 1) << (3 * b + 2)) | (((ky >> b) & 1) << (3 * b + 1))
               | (((kz >> b) & 1) << (3 * b));
        g_key[z][i] = m;
        atomicAdd(&sh[m], 1);
    }
    __syncthreads();
    g_hist[z][t] = sh[t];
}

__global__ __launch_bounds__(512) void scan_kernel() {
    __shared__ int s[512];
    const int z = blockIdx.x, t = threadIdx.x;
    const int v = g_hist[z][t];
    s[t] = v;
    __syncthreads();
    for (int off = 1; off < 512; off <<= 1) {
        const int u = (t >= off) ? s[t - off] : 0;
        __syncthreads();
        s[t] += u;
        __syncthreads();
    }
    g_offs[z][t] = s[t] - v;   // exclusive
}

__global__ __launch_bounds__(512) void scatter_kernel(const float* __restrict__ geom) {
    __shared__ unsigned short skey[NPTS];
    const int z = blockIdx.x, t = threadIdx.x;
    for (int i = t; i < NPTS; i += 512) skey[i] = (unsigned short)g_key[z][i];
    __syncthreads();
    int off = g_offs[z][t];     // thread t owns key t; stable in-index order
    for (int i = 0; i < NPTS; i++) {
        if (skey[i] == (unsigned short)t) {
            g_perm[z][off] = i;
            const float* gp = geom + ((size_t)z * NPTS + i) * 3;
            g_geoms[z][off] = make_float4(gp[0], gp[1], gp[2], 0.0f);
            off++;
        }
    }
}

__global__ __launch_bounds__(32) void bbox_kernel() {
    const int c = blockIdx.x, z = blockIdx.y, l = threadIdx.x;
    const float4 p0 = g_geoms[z][c * 64 + l];
    const float4 p1 = g_geoms[z][c * 64 + 32 + l];
    float lox = fminf(p0.x, p1.x), loy = fminf(p0.y, p1.y), loz = fminf(p0.z, p1.z);
    float hix = fmaxf(p0.x, p1.x), hiy = fmaxf(p0.y, p1.y), hiz = fmaxf(p0.z, p1.z);
#pragma unroll
    for (int o = 16; o > 0; o >>= 1) {
        lox = fminf(lox, __shfl_xor_sync(0xffffffffu, lox, o));
        loy = fminf(loy, __shfl_xor_sync(0xffffffffu, loy, o));
        loz = fminf(loz, __shfl_xor_sync(0xffffffffu, loz, o));
        hix = fmaxf(hix, __shfl_xor_sync(0xffffffffu, hix, o));
        hiy = fmaxf(hiy, __shfl_xor_sync(0xffffffffu, hiy, o));
        hiz = fmaxf(hiz, __shfl_xor_sync(0xffffffffu, hiz, o));
    }
    if (l == 0) {
        g_bbox[z][c][0] = make_float4(lox, loy, loz, 0.0f);
        g_bbox[z][c][1] = make_float4(hix, hiy, hiz, 0.0f);
    }
}

// ---------------------------------------------------------------------------
// Fused prep (R9 structure, gathered through perm): per block (z, 64 sorted
// cols): E[192][64] in smem, then H rows written fp16 to g_H (sorted layout).
// ---------------------------------------------------------------------------
__global__ __launch_bounds__(256) void prep_kernel(const float* __restrict__ feat,
                                                   const float* __restrict__ Wk) {
    extern __shared__ float sp[];
    float* s_wk = sp + PWK_F;
    float* s_E  = sp + PE_F;
    float4* s_gb = reinterpret_cast<float4*>(sp + PGB_F);

    const int z  = blockIdx.y;
    const int b0 = blockIdx.x * 64;
    const int t  = threadIdx.x;

    for (int m = t; m < 3 * 64 * 64 / 4; m += 256)
        reinterpret_cast<float4*>(s_wk)[m] = reinterpret_cast<const float4*>(Wk)[m];
    if (t < 64) s_gb[t] = g_geoms[z][b0 + t];

    const int bl = t & 63, q = t >> 6;
    const int pb = g_perm[z][b0 + bl];
    float4 fr[16];
    const float4* fp = reinterpret_cast<const float4*>(
        feat + ((size_t)z * NPTS + pb) * CIN);
#pragma unroll
    for (int c = 0; c < 16; c++) fr[c] = fp[c];
    __syncthreads();

#pragma unroll 1
    for (int n = 0; n < 48; n++) {
        const int ii = q * 48 + n;
        const float4* w = reinterpret_cast<const float4*>(s_wk + ii * 64);
        float a0 = 0.f, a1 = 0.f, a2 = 0.f, a3 = 0.f;
#pragma unroll
        for (int c = 0; c < 16; c++) {
            const float4 wv = w[c];
            a0 = fmaf(fr[c].x, wv.x, a0);
            a1 = fmaf(fr[c].y, wv.y, a1);
            a2 = fmaf(fr[c].z, wv.z, a2);
            a3 = fmaf(fr[c].w, wv.w, a3);
        }
        s_E[ii * 72 + bl] = (a0 + a1) + (a2 + a3);
    }
    __syncthreads();

    const int wrp = t >> 5, l = t & 31;
    const float4 gbA = s_gb[2 * l];
    const float4 gbB = s_gb[2 * l + 1];
    uint32_t* Hh = reinterpret_cast<uint32_t*>(g_H);

#pragma unroll 1
    for (int rr = 0; rr < 32; rr++) {
        const int r = wrp * 32 + rr;
        float v0, v1;
        if (r < 64) {
            const float2 e0 = *reinterpret_cast<const float2*>(&s_E[r * 72 + 2 * l]);
            const float2 e1 = *reinterpret_cast<const float2*>(&s_E[(64 + r) * 72 + 2 * l]);
            const float2 e2 = *reinterpret_cast<const float2*>(&s_E[(128 + r) * 72 + 2 * l]);
            v0 = fmaf(gbA.x, e0.x, fmaf(gbA.y, e1.x, gbA.z * e2.x));
            v1 = fmaf(gbB.x, e0.y, fmaf(gbB.y, e1.y, gbB.z * e2.y));
        } else {
            const float2 e = *reinterpret_cast<const float2*>(&s_E[(r - 64) * 72 + 2 * l]);
            v0 = e.x; v1 = e.y;
        }
        const __half h0 = __float2half_rn(v0);
        const __half h1 = __float2half_rn(v1);
        const size_t idx = (((size_t)z * NIP + r) * NPTS + b0) / 2 + l;
        Hh[idx] = (uint32_t)__half_as_ushort(h0) | ((uint32_t)__half_as_ushort(h1) << 16);
    }
}

// issue one chunk's B copies (256 rows x 128B, SW128-swizzled)
__device__ __forceinline__ void issue_b_copies(uint32_t bst, int z, int b0, int t) {
#pragma unroll
    for (int it = 0; it < 8; it++) {
        const int m = t + THREADS * it;          // 0..2047
        const int row = m >> 3, c16 = m & 7;
        const uint32_t dst = bst + (uint32_t)row * 128u
                           + (uint32_t)((c16 ^ (row & 7)) << 4);
        const __half* src = g_H + (((size_t)z * NIP + row) * NPTS + b0 + c16 * 8);
        cpasync16(dst, src);
    }
}

// ---------------------------------------------------------------------------
// Main: per CTA (z, 64 sorted a-rows = chunk bx): P = M @ H over ACTIVE
// chunks only (bbox distance^2 < 1). R9 pipeline: 8 warps, warp tile 32x64,
// one syncthreads per chunk, double-buffered B, in-CTA mask tile A.
// Epilogue scatters rows through perm.
// ---------------------------------------------------------------------------
__global__ __launch_bounds__(THREADS, 2) void conv_mma_kernel(float* __restrict__ out)
{
    extern __shared__ __align__(16) char smem[];
    const uint32_t su = smem_u32(smem);
    float4* g4 = reinterpret_cast<float4*>(smem);
    int* slist = reinterpret_cast<int*>(smem + LIST_OFF);

    const int z  = blockIdx.y;
    const int bx = blockIdx.x;
    const int a0 = bx * MT;
    const int t  = threadIdx.x;
    const int wid = t >> 5, lane = t & 31;
    const int m0 = (wid >> 2) * 32, n0 = (wid & 3) * 64;

    // stage sorted geometry (async)
    for (int idx = t; idx < NPTS; idx += THREADS)
        cpasync16(su + GEOM_OFF + (uint32_t)idx * 16u, &g_geoms[z][idx]);

    // build active-chunk list (warp 0)
    if (t < 32) {
        const float4 lo1 = g_bbox[z][bx][0], hi1 = g_bbox[z][bx][1];
        const float4 lo2 = g_bbox[z][t][0],  hi2 = g_bbox[z][t][1];
        const float dx = fmaxf(0.0f, fmaxf(lo1.x - hi2.x, lo2.x - hi1.x));
        const float dy = fmaxf(0.0f, fmaxf(lo1.y - hi2.y, lo2.y - hi1.y));
        const float dz = fmaxf(0.0f, fmaxf(lo1.z - hi2.z, lo2.z - hi1.z));
        const bool act = fmaf(dx, dx, fmaf(dy, dy, dz * dz)) < 1.0f;
        const unsigned msk = __ballot_sync(0xffffffffu, act);
        if (act) slist[__popc(msk & ((1u << t) - 1u))] = t;
        if (t == 0) slist[32] = __popc(msk);
    }
    __syncthreads();
    const int nact = slist[32];

    // first B chunk copies (same cp.async group as geometry)
    issue_b_copies(su + B_OFF, z, slist[0] * KC, t);
    asm volatile("cp.async.commit_group;" ::: "memory");
    asm volatile("cp.async.wait_group 0;" ::: "memory");
    __syncthreads();

    // maskgen consts: thread t -> row rg (0..63), k-quarter sg
    const int rg = t >> 2, sg = t & 3;
    const float4 ga = g4[a0 + rg];
    const uint32_t aw_base = su + A_OFF + (uint32_t)rg * 128u;
    const uint32_t rx = (uint32_t)(rg & 7);

    // ldsm lane bases
    const int rowA = m0 + ((lane >> 3) & 1) * 8 + (lane & 7);
    const uint32_t sA = (uint32_t)(lane >> 4), rxA = (uint32_t)(rowA & 7);
    const int rowB = n0 + ((lane >> 4) & 1) * 8 + (lane & 7);
    const uint32_t sB = (uint32_t)((lane >> 3) & 1), rxB = (uint32_t)(rowB & 7);

    float d[2][8][4];
#pragma unroll
    for (int mt = 0; mt < 2; mt++)
#pragma unroll
        for (int nt = 0; nt < 8; nt++)
#pragma unroll
            for (int r = 0; r < 4; r++) d[mt][nt][r] = 0.0f;

#pragma unroll 1
    for (int j = 0; j < nact; j++) {
        const uint32_t p = (uint32_t)(j & 1);
        const int b0 = slist[j] * KC;

        // ---- mask tile A[64 x 64] fp16 (SW128), diff-form norm test ----
        {
            const uint32_t ast = aw_base + p * A_STG;
#pragma unroll
            for (int v = 0; v < 8; v++) {
                const int veff = (v + sg) & 7;
                const int k0 = sg * 16 + 2 * veff;
                const float4 q0 = g4[b0 + k0];
                const float4 q1 = g4[b0 + k0 + 1];
                const float dx0 = q0.x - ga.x, dy0 = q0.y - ga.y, dz0 = q0.z - ga.z;
                const float dx1 = q1.x - ga.x, dy1 = q1.y - ga.y, dz1 = q1.z - ga.z;
                const float nn0 = fmaf(dx0, dx0, fmaf(dy0, dy0, dz0 * dz0));
                const float nn1 = fmaf(dx1, dx1, fmaf(dy1, dy1, dz1 * dz1));
                const uint32_t val = (nn0 < 1.0f ? 0x3C00u : 0u)
                                   | (nn1 < 1.0f ? 0x3C000000u : 0u);
                const uint32_t bc = (uint32_t)(2 * k0);
                sts32(ast + (((bc >> 4) ^ rx) << 4) + (bc & 15u), val);
            }
        }
        if (j > 0)
            asm volatile("cp.async.wait_group 0;" ::: "memory");   // B(j) ready
        __syncthreads();   // A(p)+B(p) visible; all warps done with stage p^1

        if (j + 1 < nact) {
            issue_b_copies(su + B_OFF + (p ^ 1u) * B_STG, z, slist[j + 1] * KC, t);
            asm volatile("cp.async.commit_group;" ::: "memory");
        }

        // ---- ldmatrix + 64 HMMA per warp ----
        {
            const uint32_t Ast = su + A_OFF + p * A_STG;
            const uint32_t Bst = su + B_OFF + p * B_STG;
#pragma unroll
            for (int kk = 0; kk < 4; kk++) {
                uint32_t af[2][4];
#pragma unroll
                for (int mt = 0; mt < 2; mt++)
                    ldsm_x4(af[mt][0], af[mt][1], af[mt][2], af[mt][3],
                            Ast + (uint32_t)(rowA + mt * 16) * 128u
                                + ((((uint32_t)kk * 2u + sA) ^ rxA) << 4));
#pragma unroll
                for (int ntp = 0; ntp < 4; ntp++) {
                    uint32_t b0r, b1r, b2r, b3r;
                    ldsm_x4(b0r, b1r, b2r, b3r,
                            Bst + (uint32_t)(rowB + ntp * 16) * 128u
                               + ((((uint32_t)kk * 2u + sB) ^ rxB) << 4));
#pragma unroll
                    for (int mt = 0; mt < 2; mt++) {
                        mma16816(d[mt][2*ntp][0], d[mt][2*ntp][1], d[mt][2*ntp][2], d[mt][2*ntp][3],
                                 af[mt][0], af[mt][1], af[mt][2], af[mt][3], b0r, b1r);
                        mma16816(d[mt][2*ntp+1][0], d[mt][2*ntp+1][1], d[mt][2*ntp+1][2], d[mt][2*ntp+1][3],
                                 af[mt][0], af[mt][1], af[mt][2], af[mt][3], b2r, b3r);
                    }
                }
            }
        }
    }

    // ---- epilogue: P (overlays A/B region), combine, scatter via perm ----
    __syncthreads();
    float* P = reinterpret_cast<float*>(smem + A_OFF);   // [64][260]
    const int fr = lane >> 2, fc = lane & 3;
#pragma unroll
    for (int mt = 0; mt < 2; mt++) {
#pragma unroll
        for (int nt = 0; nt < 8; nt++) {
            const int R0 = m0 + mt * 16 + fr;
            const int C  = n0 + nt * 8 + 2 * fc;
            *reinterpret_cast<float2*>(P + R0 * 260 + C)       = make_float2(d[mt][nt][0], d[mt][nt][1]);
            *reinterpret_cast<float2*>(P + (R0 + 8) * 260 + C) = make_float2(d[mt][nt][2], d[mt][nt][3]);
        }
    }
    __syncthreads();

    {
        const int al = t >> 2, iq = t & 3;
        const float4 ga4 = g4[a0 + al];
        const int pa = g_perm[z][a0 + al];
        float* orow = out + ((size_t)z * NPTS + pa) * 64;
        const float* Pr = P + al * 260;
#pragma unroll
        for (int u = 0; u < 4; u++) {
            const int i0 = iq * 16 + u * 4;
            const float4 vc = *reinterpret_cast<const float4*>(Pr + i0);
            const float4 v1 = *reinterpret_cast<const float4*>(Pr + 64 + i0);
            const float4 v2 = *reinterpret_cast<const float4*>(Pr + 128 + i0);
            const float4 v3 = *reinterpret_cast<const float4*>(Pr + 192 + i0);
            float4 o;
            o.x = fmaf(-ga4.z, v3.x, fmaf(-ga4.y, v2.x, fmaf(-ga4.x, v1.x, vc.x)));
            o.y = fmaf(-ga4.z, v3.y, fmaf(-ga4.y, v2.y, fmaf(-ga4.x, v1.y, vc.y)));
            o.z = fmaf(-ga4.z, v3.z, fmaf(-ga4.y, v2.z, fmaf(-ga4.x, v1.z, vc.z)));
            o.w = fmaf(-ga4.z, v3.w, fmaf(-ga4.y, v2.w, fmaf(-ga4.x, v1.w, vc.w)));
            *reinterpret_cast<float4*>(orow + i0) = o;
        }
    }
}

// ---------------------------------------------------------------------------
// Launcher. Inputs: features [8,2048,64] f32, geometry [8,2048,3] f32,
// Wk [3,64,64] f32. Output [8,2048,64] f32.
// ---------------------------------------------------------------------------
extern "C" void kernel_launch(void* const* d_in, const int* in_sizes, int n_in,
                              void* d_out, int out_size) {
    const float* feat = (const float*)d_in[0];
    const float* geom = (const float*)d_in[1];
    const float* Wk   = (const float*)d_in[2];
    float* out = (float*)d_out;
    (void)in_sizes; (void)n_in; (void)out_size;

    cudaFuncSetAttribute(prep_kernel,
                         cudaFuncAttributeMaxDynamicSharedMemorySize, SMEM_PREP);
    cudaFuncSetAttribute(conv_mma_kernel,
                         cudaFuncAttributeMaxDynamicSharedMemorySize, SMEM_MAIN);

    key_hist_kernel<<<BATCH, 512>>>(geom);
    scan_kernel<<<BATCH, 512>>>();
    scatter_kernel<<<BATCH, 512>>>(geom);
    bbox_kernel<<<dim3(NCHUNK, BATCH), 32>>>();
    prep_kernel<<<dim3(NPTS / 64, BATCH), 256, SMEM_PREP>>>(feat, Wk);
    conv_mma_kernel<<<dim3(NPTS / MT, BATCH), THREADS, SMEM_MAIN>>>(out);
}

// round 12
// speedup vs baseline: 1.8182x; 1.8182x over previous
#include <cuda_runtime.h>
#include <cuda_fp16.h>
#include <cstdint>

#define BATCH 8
#define NPTS  2048
#define CIN   64
#define NIP   256            // H width: [c(64) | e(192)]
#define MT    64             // a-rows per CTA
#define KC    64             // b's per chunk
#define NCHUNK (NPTS / KC)   // 32
#define THREADS 256

// Static device scratch (allocation is forbidden)
__device__ __align__(128) __half g_H[(size_t)BATCH * NIP * NPTS];  // [z][i'][b] fp16
__device__ float4 g_g4[BATCH][NPTS];                               // packed geometry

// ---- main-kernel smem layout (bytes) ----
#define A_OFF    0u                  // 2 x 8192 (64 rows x 128B, SW128)
#define A_STG    8192u
#define B_OFF    16384u              // 3 x 32768 (256 rows x 128B, SW128)
#define B_STG    32768u
#define SMEM_MAIN (B_OFF + 3u * B_STG)   // 114688 -> 2 CTAs/SM

// ---- prep-kernel smem (floats) ----
#define PWK_F   0
#define PE_F    12288                // E tile 192 x 72
#define PGB_F   26112                // 64 x float4
#define SMEM_PREP ((26112 + 256) * 4)

__device__ __forceinline__ uint32_t smem_u32(const void* p) {
    uint32_t a;
    asm("{ .reg .u64 t; cvta.to.shared.u64 t, %1; cvt.u32.u64 %0, t; }" : "=r"(a) : "l"(p));
    return a;
}
__device__ __forceinline__ void cpasync16(uint32_t dst, const void* src) {
    asm volatile("cp.async.cg.shared.global [%0], [%1], 16;" :: "r"(dst), "l"(src) : "memory");
}
__device__ __forceinline__ void sts32(uint32_t a, uint32_t v) {
    asm volatile("st.shared.b32 [%0], %1;" :: "r"(a), "r"(v) : "memory");
}
__device__ __forceinline__ void ldsm_x4(uint32_t& r0, uint32_t& r1, uint32_t& r2, uint32_t& r3,
                                        uint32_t addr) {
    asm volatile("ldmatrix.sync.aligned.m8n8.x4.shared.b16 {%0,%1,%2,%3}, [%4];"
                 : "=r"(r0), "=r"(r1), "=r"(r2), "=r"(r3) : "r"(addr));
}
__device__ __forceinline__ void mma16816(float& d0, float& d1, float& d2, float& d3,
                                         uint32_t a0, uint32_t a1, uint32_t a2, uint32_t a3,
                                         uint32_t b0, uint32_t b1) {
    asm volatile(
        "mma.sync.aligned.m16n8k16.row.col.f32.f16.f16.f32 "
        "{%0,%1,%2,%3}, {%4,%5,%6,%7}, {%8,%9}, {%0,%1,%2,%3};"
        : "+f"(d0), "+f"(d1), "+f"(d2), "+f"(d3)
        : "r"(a0), "r"(a1), "r"(a2), "r"(a3), "r"(b0), "r"(b1));
}

// ---------------------------------------------------------------------------
// Fused prep (R9): per block (z, b-tile of 64): E[192][64] in smem, then
// H rows (c for r<64, e shifted for r>=64) as fp16 to g_H. Also writes the
// packed float4 geometry g_g4 for the main kernel.
// ---------------------------------------------------------------------------
__global__ __launch_bounds__(256) void prep_kernel(const float* __restrict__ feat,
                                                   const float* __restrict__ geom,
                                                   const float* __restrict__ Wk) {
    extern __shared__ float sp[];
    float* s_wk = sp + PWK_F;
    float* s_E  = sp + PE_F;
    float4* s_gb = reinterpret_cast<float4*>(sp + PGB_F);

    const int z  = blockIdx.y;
    const int b0 = blockIdx.x * 64;
    const int t  = threadIdx.x;

    for (int m = t; m < 3 * 64 * 64 / 4; m += 256)
        reinterpret_cast<float4*>(s_wk)[m] = reinterpret_cast<const float4*>(Wk)[m];
    if (t < 64) {
        const float* gp = geom + ((size_t)z * NPTS + b0 + t) * 3;
        const float4 v = make_float4(gp[0], gp[1], gp[2], 0.0f);
        s_gb[t] = v;
        g_g4[z][b0 + t] = v;
    }

    const int bl = t & 63, q = t >> 6;
    float4 fr[16];
    const float4* fp = reinterpret_cast<const float4*>(
        feat + ((size_t)z * NPTS + b0 + bl) * CIN);
#pragma unroll
    for (int c = 0; c < 16; c++) fr[c] = fp[c];
    __syncthreads();

#pragma unroll 1
    for (int n = 0; n < 48; n++) {
        const int ii = q * 48 + n;
        const float4* w = reinterpret_cast<const float4*>(s_wk + ii * 64);
        float a0 = 0.f, a1 = 0.f, a2 = 0.f, a3 = 0.f;
#pragma unroll
        for (int c = 0; c < 16; c++) {
            const float4 wv = w[c];
            a0 = fmaf(fr[c].x, wv.x, a0);
            a1 = fmaf(fr[c].y, wv.y, a1);
            a2 = fmaf(fr[c].z, wv.z, a2);
            a3 = fmaf(fr[c].w, wv.w, a3);
        }
        s_E[ii * 72 + bl] = (a0 + a1) + (a2 + a3);
    }
    __syncthreads();

    const int wrp = t >> 5, l = t & 31;
    const float4 gbA = s_gb[2 * l];
    const float4 gbB = s_gb[2 * l + 1];
    uint32_t* Hh = reinterpret_cast<uint32_t*>(g_H);

#pragma unroll 1
    for (int rr = 0; rr < 32; rr++) {
        const int r = wrp * 32 + rr;
        float v0, v1;
        if (r < 64) {
            const float2 e0 = *reinterpret_cast<const float2*>(&s_E[r * 72 + 2 * l]);
            const float2 e1 = *reinterpret_cast<const float2*>(&s_E[(64 + r) * 72 + 2 * l]);
            const float2 e2 = *reinterpret_cast<const float2*>(&s_E[(128 + r) * 72 + 2 * l]);
            v0 = fmaf(gbA.x, e0.x, fmaf(gbA.y, e1.x, gbA.z * e2.x));
            v1 = fmaf(gbB.x, e0.y, fmaf(gbB.y, e1.y, gbB.z * e2.y));
        } else {
            const float2 e = *reinterpret_cast<const float2*>(&s_E[(r - 64) * 72 + 2 * l]);
            v0 = e.x; v1 = e.y;
        }
        const __half h0 = __float2half_rn(v0);
        const __half h1 = __float2half_rn(v1);
        const size_t idx = (((size_t)z * NIP + r) * NPTS + b0) / 2 + l;
        Hh[idx] = (uint32_t)__half_as_ushort(h0) | ((uint32_t)__half_as_ushort(h1) << 16);
    }
}

// issue one chunk's B copies (256 rows x 128B, SW128-swizzled)
__device__ __forceinline__ void issue_b_copies(uint32_t bst, int z, int b0, int t) {
#pragma unroll
    for (int it = 0; it < 8; it++) {
        const int m = t + THREADS * it;          // 0..2047
        const int row = m >> 3, c16 = m & 7;
        const uint32_t dst = bst + (uint32_t)row * 128u
                           + (uint32_t)((c16 ^ (row & 7)) << 4);
        const __half* src = g_H + (((size_t)z * NIP + row) * NPTS + b0 + c16 * 8);
        cpasync16(dst, src);
    }
}

// ---------------------------------------------------------------------------
// Main: per CTA (z, 64 a-rows): P[64 x 256] = M @ H (fp16 HMMA, fp32 accum).
// 8 warps, warp tile 32x64, one syncthreads per chunk, TRIPLE-buffered B
// (prefetch depth 2), geometry via __ldg of packed g_g4 (L1-resident).
// Order per chunk: maskgen -> wait B -> sync -> issue B(j+2) -> MMA.
// ---------------------------------------------------------------------------
__global__ __launch_bounds__(THREADS, 2) void conv_mma_kernel(float* __restrict__ out)
{
    extern __shared__ __align__(16) char smem[];
    const uint32_t su = smem_u32(smem);

    const int z  = blockIdx.y;
    const int a0 = blockIdx.x * MT;
    const int t  = threadIdx.x;
    const int wid = t >> 5, lane = t & 31;
    const int m0 = (wid >> 2) * 32, n0 = (wid & 3) * 64;

    // prologue: prefetch chunks 0 and 1
    issue_b_copies(su + B_OFF, z, 0, t);
    asm volatile("cp.async.commit_group;" ::: "memory");
    issue_b_copies(su + B_OFF + B_STG, z, KC, t);
    asm volatile("cp.async.commit_group;" ::: "memory");

    // maskgen consts: thread t -> row rg (0..63), k-quarter sg
    const int rg = t >> 2, sg = t & 3;
    const float4 ga = __ldg(&g_g4[z][a0 + rg]);
    const uint32_t aw_base = su + A_OFF + (uint32_t)rg * 128u;
    const uint32_t rx = (uint32_t)(rg & 7);

    // ldsm lane bases
    const int rowA = m0 + ((lane >> 3) & 1) * 8 + (lane & 7);
    const uint32_t sA = (uint32_t)(lane >> 4), rxA = (uint32_t)(rowA & 7);
    const int rowB = n0 + ((lane >> 4) & 1) * 8 + (lane & 7);
    const uint32_t sB = (uint32_t)((lane >> 3) & 1), rxB = (uint32_t)(rowB & 7);

    float d[2][8][4];
#pragma unroll
    for (int mt = 0; mt < 2; mt++)
#pragma unroll
        for (int nt = 0; nt < 8; nt++)
#pragma unroll
            for (int r = 0; r < 4; r++) d[mt][nt][r] = 0.0f;

    uint32_t bs = 0;   // B stage of current chunk (mod-3 ring)

#pragma unroll 1
    for (int j = 0; j < NCHUNK; j++) {
        const uint32_t p = (uint32_t)(j & 1);
        const int b0 = j * KC;

        // ---- mask tile A[64 x 64] fp16 (SW128); geometry via __ldg ----
        {
            const uint32_t ast = aw_base + p * A_STG;
#pragma unroll
            for (int v = 0; v < 8; v++) {
                const int veff = (v + sg) & 7;
                const int k0 = sg * 16 + 2 * veff;
                const float4 q0 = __ldg(&g_g4[z][b0 + k0]);
                const float4 q1 = __ldg(&g_g4[z][b0 + k0 + 1]);
                const float dx0 = q0.x - ga.x, dy0 = q0.y - ga.y, dz0 = q0.z - ga.z;
                const float dx1 = q1.x - ga.x, dy1 = q1.y - ga.y, dz1 = q1.z - ga.z;
                const float nn0 = fmaf(dx0, dx0, fmaf(dy0, dy0, dz0 * dz0));
                const float nn1 = fmaf(dx1, dx1, fmaf(dy1, dy1, dz1 * dz1));
                const uint32_t val = (nn0 < 1.0f ? 0x3C00u : 0u)
                                   | (nn1 < 1.0f ? 0x3C000000u : 0u);
                const uint32_t bc = (uint32_t)(2 * k0);
                sts32(ast + (((bc >> 4) ^ rx) << 4) + (bc & 15u), val);
            }
        }

        // B(j) must be complete (own copies); barrier makes everyone's visible
        if (j + 1 < NCHUNK)
            asm volatile("cp.async.wait_group 1;" ::: "memory");
        else
            asm volatile("cp.async.wait_group 0;" ::: "memory");
        __syncthreads();

        // prefetch chunk j+2 into stage (bs+2)%3
        if (j + 2 < NCHUNK) {
            uint32_t ns = bs + 2;
            if (ns >= 3) ns -= 3;
            issue_b_copies(su + B_OFF + ns * B_STG, z, b0 + 2 * KC, t);
            asm volatile("cp.async.commit_group;" ::: "memory");
        }

        // ---- ldmatrix + 64 HMMA per warp ----
        {
            const uint32_t Ast = su + A_OFF + p * A_STG;
            const uint32_t Bst = su + B_OFF + bs * B_STG;
#pragma unroll
            for (int kk = 0; kk < 4; kk++) {
                uint32_t af[2][4];
#pragma unroll
                for (int mt = 0; mt < 2; mt++)
                    ldsm_x4(af[mt][0], af[mt][1], af[mt][2], af[mt][3],
                            Ast + (uint32_t)(rowA + mt * 16) * 128u
                                + ((((uint32_t)kk * 2u + sA) ^ rxA) << 4));
#pragma unroll
                for (int ntp = 0; ntp < 4; ntp++) {
                    uint32_t b0r, b1r, b2r, b3r;
                    ldsm_x4(b0r, b1r, b2r, b3r,
                            Bst + (uint32_t)(rowB + ntp * 16) * 128u
                               + ((((uint32_t)kk * 2u + sB) ^ rxB) << 4));
#pragma unroll
                    for (int mt = 0; mt < 2; mt++) {
                        mma16816(d[mt][2*ntp][0], d[mt][2*ntp][1], d[mt][2*ntp][2], d[mt][2*ntp][3],
                                 af[mt][0], af[mt][1], af[mt][2], af[mt][3], b0r, b1r);
                        mma16816(d[mt][2*ntp+1][0], d[mt][2*ntp+1][1], d[mt][2*ntp+1][2], d[mt][2*ntp+1][3],
                                 af[mt][0], af[mt][1], af[mt][2], af[mt][3], b2r, b3r);
                    }
                }
            }
        }

        bs = (bs + 1 == 3) ? 0 : bs + 1;
    }

    // ---- epilogue: P (overlays A/B region), combine, store ----
    __syncthreads();
    float* P = reinterpret_cast<float*>(smem);   // [64][260]
    const int fr = lane >> 2, fc = lane & 3;
#pragma unroll
    for (int mt = 0; mt < 2; mt++) {
#pragma unroll
        for (int nt = 0; nt < 8; nt++) {
            const int R0 = m0 + mt * 16 + fr;
            const int C  = n0 + nt * 8 + 2 * fc;
            *reinterpret_cast<float2*>(P + R0 * 260 + C)       = make_float2(d[mt][nt][0], d[mt][nt][1]);
            *reinterpret_cast<float2*>(P + (R0 + 8) * 260 + C) = make_float2(d[mt][nt][2], d[mt][nt][3]);
        }
    }
    __syncthreads();

    {
        const int al = t >> 2, iq = t & 3;
        const float4 ga4 = __ldg(&g_g4[z][a0 + al]);
        float* orow = out + ((size_t)z * NPTS + a0 + al) * 64;
        const float* Pr = P + al * 260;
#pragma unroll
        for (int u = 0; u < 4; u++) {
            const int i0 = iq * 16 + u * 4;
            const float4 vc = *reinterpret_cast<const float4*>(Pr + i0);
            const float4 v1 = *reinterpret_cast<const float4*>(Pr + 64 + i0);
            const float4 v2 = *reinterpret_cast<const float4*>(Pr + 128 + i0);
            const float4 v3 = *reinterpret_cast<const float4*>(Pr + 192 + i0);
            float4 o;
            o.x = fmaf(-ga4.z, v3.x, fmaf(-ga4.y, v2.x, fmaf(-ga4.x, v1.x, vc.x)));
            o.y = fmaf(-ga4.z, v3.y, fmaf(-ga4.y, v2.y, fmaf(-ga4.x, v1.y, vc.y)));
            o.z = fmaf(-ga4.z, v3.z, fmaf(-ga4.y, v2.z, fmaf(-ga4.x, v1.z, vc.z)));
            o.w = fmaf(-ga4.z, v3.w, fmaf(-ga4.y, v2.w, fmaf(-ga4.x, v1.w, vc.w)));
            *reinterpret_cast<float4*>(orow + i0) = o;
        }
    }
}

// ---------------------------------------------------------------------------
// Launcher. Inputs: features [8,2048,64] f32, geometry [8,2048,3] f32,
// Wk [3,64,64] f32. Output [8,2048,64] f32.
// ---------------------------------------------------------------------------
extern "C" void kernel_launch(void* const* d_in, const int* in_sizes, int n_in,
                              void* d_out, int out_size) {
    const float* feat = (const float*)d_in[0];
    const float* geom = (const float*)d_in[1];
    const float* Wk   = (const float*)d_in[2];
    float* out = (float*)d_out;
    (void)in_sizes; (void)n_in; (void)out_size;

    cudaFuncSetAttribute(prep_kernel,
                         cudaFuncAttributeMaxDynamicSharedMemorySize, SMEM_PREP);
    cudaFuncSetAttribute(conv_mma_kernel,
                         cudaFuncAttributeMaxDynamicSharedMemorySize, SMEM_MAIN);

    prep_kernel<<<dim3(NPTS / 64, BATCH), 256, SMEM_PREP>>>(feat, geom, Wk);
    conv_mma_kernel<<<dim3(NPTS / MT, BATCH), THREADS, SMEM_MAIN>>>(out);
}

// round 13
// speedup vs baseline: 2.1462x; 1.1804x over previous
#include <cuda_runtime.h>
#include <cuda_fp16.h>
#include <cstdint>

#define BATCH 8
#define NPTS  2048
#define CIN   64
#define NIP   256            // H width: [c(64) | e(192)]
#define MT    64             // a-rows per CTA
#define KC    64             // b's per chunk
#define NCHUNK (NPTS / KC)   // 32
#define THREADS 256

// Static device scratch (allocation is forbidden)
__device__ __align__(128) __half g_H[(size_t)BATCH * NIP * NPTS];  // [z][i'][b] fp16

// ---- main-kernel smem layout (bytes) ----
#define GEOM_OFF 0u                  // 2048 x float4 = 32768
#define A_OFF    32768u              // 2 x 8192 (64 rows x 128B, SW128)
#define A_STG    8192u
#define B_OFF    49152u              // 2 x 32768 (256 rows x 128B, SW128)
#define B_STG    32768u
#define SMEM_MAIN (B_OFF + 2u * B_STG)   // 114688 -> 2 CTAs/SM

// ---- prep-kernel smem (floats) ----
#define PWK_F   0
#define PE_F    12288                // E tile 192 x 72
#define PGB_F   26112                // 64 x float4
#define SMEM_PREP ((26112 + 256) * 4)

__device__ __forceinline__ uint32_t smem_u32(const void* p) {
    uint32_t a;
    asm("{ .reg .u64 t; cvta.to.shared.u64 t, %1; cvt.u32.u64 %0, t; }" : "=r"(a) : "l"(p));
    return a;
}
__device__ __forceinline__ void cpasync16(uint32_t dst, const void* src) {
    asm volatile("cp.async.cg.shared.global [%0], [%1], 16;" :: "r"(dst), "l"(src) : "memory");
}
__device__ __forceinline__ void sts32(uint32_t a, uint32_t v) {
    asm volatile("st.shared.b32 [%0], %1;" :: "r"(a), "r"(v) : "memory");
}
__device__ __forceinline__ void ldsm_x4(uint32_t& r0, uint32_t& r1, uint32_t& r2, uint32_t& r3,
                                        uint32_t addr) {
    asm volatile("ldmatrix.sync.aligned.m8n8.x4.shared.b16 {%0,%1,%2,%3}, [%4];"
                 : "=r"(r0), "=r"(r1), "=r"(r2), "=r"(r3) : "r"(addr));
}
__device__ __forceinline__ void mma16816(float& d0, float& d1, float& d2, float& d3,
                                         uint32_t a0, uint32_t a1, uint32_t a2, uint32_t a3,
                                         uint32_t b0, uint32_t b1) {
    asm volatile(
        "mma.sync.aligned.m16n8k16.row.col.f32.f16.f16.f32 "
        "{%0,%1,%2,%3}, {%4,%5,%6,%7}, {%8,%9}, {%0,%1,%2,%3};"
        : "+f"(d0), "+f"(d1), "+f"(d2), "+f"(d3)
        : "r"(a0), "r"(a1), "r"(a2), "r"(a3), "r"(b0), "r"(b1));
}

// ---------------------------------------------------------------------------
// Fused prep (R9 verbatim): per block (z, b-tile of 64):
//   E[192][64] in smem, then H rows (c for r<64, e shifted for r>=64),
//   written as fp16 straight to g_H [z][i'][b].
// ---------------------------------------------------------------------------
__global__ __launch_bounds__(256) void prep_kernel(const float* __restrict__ feat,
                                                   const float* __restrict__ geom,
                                                   const float* __restrict__ Wk) {
    extern __shared__ float sp[];
    float* s_wk = sp + PWK_F;
    float* s_E  = sp + PE_F;
    float4* s_gb = reinterpret_cast<float4*>(sp + PGB_F);

    const int z  = blockIdx.y;
    const int b0 = blockIdx.x * 64;
    const int t  = threadIdx.x;

    for (int m = t; m < 3 * 64 * 64 / 4; m += 256)
        reinterpret_cast<float4*>(s_wk)[m] = reinterpret_cast<const float4*>(Wk)[m];
    if (t < 64) {
        const float* gp = geom + ((size_t)z * NPTS + b0 + t) * 3;
        s_gb[t] = make_float4(gp[0], gp[1], gp[2], 0.0f);
    }

    const int bl = t & 63, q = t >> 6;
    float4 fr[16];
    const float4* fp = reinterpret_cast<const float4*>(
        feat + ((size_t)z * NPTS + b0 + bl) * CIN);
#pragma unroll
    for (int c = 0; c < 16; c++) fr[c] = fp[c];
    __syncthreads();

#pragma unroll 1
    for (int n = 0; n < 48; n++) {
        const int ii = q * 48 + n;
        const float4* w = reinterpret_cast<const float4*>(s_wk + ii * 64);
        float a0 = 0.f, a1 = 0.f, a2 = 0.f, a3 = 0.f;
#pragma unroll
        for (int c = 0; c < 16; c++) {
            const float4 wv = w[c];
            a0 = fmaf(fr[c].x, wv.x, a0);
            a1 = fmaf(fr[c].y, wv.y, a1);
            a2 = fmaf(fr[c].z, wv.z, a2);
            a3 = fmaf(fr[c].w, wv.w, a3);
        }
        s_E[ii * 72 + bl] = (a0 + a1) + (a2 + a3);
    }
    __syncthreads();

    const int wrp = t >> 5, l = t & 31;
    const float4 gbA = s_gb[2 * l];
    const float4 gbB = s_gb[2 * l + 1];
    uint32_t* Hh = reinterpret_cast<uint32_t*>(g_H);

#pragma unroll 1
    for (int rr = 0; rr < 32; rr++) {
        const int r = wrp * 32 + rr;
        float v0, v1;
        if (r < 64) {
            const float2 e0 = *reinterpret_cast<const float2*>(&s_E[r * 72 + 2 * l]);
            const float2 e1 = *reinterpret_cast<const float2*>(&s_E[(64 + r) * 72 + 2 * l]);
            const float2 e2 = *reinterpret_cast<const float2*>(&s_E[(128 + r) * 72 + 2 * l]);
            v0 = fmaf(gbA.x, e0.x, fmaf(gbA.y, e1.x, gbA.z * e2.x));
            v1 = fmaf(gbB.x, e0.y, fmaf(gbB.y, e1.y, gbB.z * e2.y));
        } else {
            const float2 e = *reinterpret_cast<const float2*>(&s_E[(r - 64) * 72 + 2 * l]);
            v0 = e.x; v1 = e.y;
        }
        const __half h0 = __float2half_rn(v0);
        const __half h1 = __float2half_rn(v1);
        const size_t idx = (((size_t)z * NIP + r) * NPTS + b0) / 2 + l;
        Hh[idx] = (uint32_t)__half_as_ushort(h0) | ((uint32_t)__half_as_ushort(h1) << 16);
    }
}

// issue one chunk's B copies (256 rows x 128B, SW128-swizzled)
__device__ __forceinline__ void issue_b_copies(uint32_t bst, int z, int b0, int t) {
#pragma unroll
    for (int it = 0; it < 8; it++) {
        const int m = t + THREADS * it;          // 0..2047
        const int row = m >> 3, c16 = m & 7;
        const uint32_t dst = bst + (uint32_t)row * 128u
                           + (uint32_t)((c16 ^ (row & 7)) << 4);
        const __half* src = g_H + (((size_t)z * NIP + row) * NPTS + b0 + c16 * 8);
        cpasync16(dst, src);
    }
}

// ---------------------------------------------------------------------------
// Main (R9 + one reorder): per CTA (z, 64 a-rows): P[64 x 256] = M @ H
// (fp16 HMMA, fp32 accum). 8 warps, warp tile 32x64, one syncthreads per
// chunk, double-buffered B, in-CTA mask tile A from whole-z smem geometry.
// Per-chunk order: maskgen -> wait B(j) -> sync -> issue B(j+1) -> MMA
// (maskgen hides residual B copy latency).
// ---------------------------------------------------------------------------
__global__ __launch_bounds__(THREADS, 2) void conv_mma_kernel(
    const float* __restrict__ geom, float* __restrict__ out)
{
    extern __shared__ __align__(16) char smem[];
    const uint32_t su = smem_u32(smem);
    float4* g4 = reinterpret_cast<float4*>(smem);

    const int z  = blockIdx.y;
    const int a0 = blockIdx.x * MT;
    const int t  = threadIdx.x;
    const int wid = t >> 5, lane = t & 31;
    const int m0 = (wid >> 2) * 32, n0 = (wid & 3) * 64;

    const float* gz = geom + (size_t)z * NPTS * 3;

    // prologue: chunk-0 B copies + stage whole-z geometry as float4
    issue_b_copies(su + B_OFF, z, 0, t);
    asm volatile("cp.async.commit_group;" ::: "memory");
    {
        float* gf = reinterpret_cast<float*>(smem);
        for (int idx = t; idx < NPTS * 3; idx += THREADS)
            gf[(idx / 3) * 4 + (idx % 3)] = gz[idx];
    }
    __syncthreads();

    // maskgen consts: thread t -> row rg (0..63), k-quarter sg
    const int rg = t >> 2, sg = t & 3;
    const float4 ga = g4[a0 + rg];
    const uint32_t aw_base = su + A_OFF + (uint32_t)rg * 128u;
    const uint32_t rx = (uint32_t)(rg & 7);

    // ldsm lane bases
    const int rowA = m0 + ((lane >> 3) & 1) * 8 + (lane & 7);
    const uint32_t sA = (uint32_t)(lane >> 4), rxA = (uint32_t)(rowA & 7);
    const int rowB = n0 + ((lane >> 4) & 1) * 8 + (lane & 7);
    const uint32_t sB = (uint32_t)((lane >> 3) & 1), rxB = (uint32_t)(rowB & 7);

    float d[2][8][4];
#pragma unroll
    for (int mt = 0; mt < 2; mt++)
#pragma unroll
        for (int nt = 0; nt < 8; nt++)
#pragma unroll
            for (int r = 0; r < 4; r++) d[mt][nt][r] = 0.0f;

#pragma unroll 1
    for (int i = 0; i < NCHUNK; i++) {
        const uint32_t p = (uint32_t)(i & 1);
        const int b0 = i * KC;

        // ---- mask tile A[64 x 64] fp16 (SW128), diff-form norm test ----
        // (independent of B(j); runs while B(j) copies drain)
        {
            const uint32_t ast = aw_base + p * A_STG;
#pragma unroll
            for (int v = 0; v < 8; v++) {
                const int veff = (v + sg) & 7;
                const int k0 = sg * 16 + 2 * veff;
                const float4 q0 = g4[b0 + k0];
                const float4 q1 = g4[b0 + k0 + 1];
                const float dx0 = q0.x - ga.x, dy0 = q0.y - ga.y, dz0 = q0.z - ga.z;
                const float dx1 = q1.x - ga.x, dy1 = q1.y - ga.y, dz1 = q1.z - ga.z;
                const float nn0 = fmaf(dx0, dx0, fmaf(dy0, dy0, dz0 * dz0));
                const float nn1 = fmaf(dx1, dx1, fmaf(dy1, dy1, dz1 * dz1));
                const uint32_t val = (nn0 < 1.0f ? 0x3C00u : 0u)
                                   | (nn1 < 1.0f ? 0x3C000000u : 0u);
                const uint32_t bc = (uint32_t)(2 * k0);
                sts32(ast + (((bc >> 4) ^ rx) << 4) + (bc & 15u), val);
            }
        }

        asm volatile("cp.async.wait_group 0;" ::: "memory");   // B(j) complete
        __syncthreads();   // A(p)+B(p) visible; all warps done with stage p^1

        if (i + 1 < NCHUNK) {
            issue_b_copies(su + B_OFF + (p ^ 1u) * B_STG, z, b0 + KC, t);
            asm volatile("cp.async.commit_group;" ::: "memory");
        }

        // ---- ldmatrix + 64 HMMA per warp ----
        {
            const uint32_t Ast = su + A_OFF + p * A_STG;
            const uint32_t Bst = su + B_OFF + p * B_STG;
#pragma unroll
            for (int kk = 0; kk < 4; kk++) {
                uint32_t af[2][4];
#pragma unroll
                for (int mt = 0; mt < 2; mt++)
                    ldsm_x4(af[mt][0], af[mt][1], af[mt][2], af[mt][3],
                            Ast + (uint32_t)(rowA + mt * 16) * 128u
                                + ((((uint32_t)kk * 2u + sA) ^ rxA) << 4));
#pragma unroll
                for (int ntp = 0; ntp < 4; ntp++) {
                    uint32_t b0r, b1r, b2r, b3r;
                    ldsm_x4(b0r, b1r, b2r, b3r,
                            Bst + (uint32_t)(rowB + ntp * 16) * 128u
                               + ((((uint32_t)kk * 2u + sB) ^ rxB) << 4));
#pragma unroll
                    for (int mt = 0; mt < 2; mt++) {
                        mma16816(d[mt][2*ntp][0], d[mt][2*ntp][1], d[mt][2*ntp][2], d[mt][2*ntp][3],
                                 af[mt][0], af[mt][1], af[mt][2], af[mt][3], b0r, b1r);
                        mma16816(d[mt][2*ntp+1][0], d[mt][2*ntp+1][1], d[mt][2*ntp+1][2], d[mt][2*ntp+1][3],
                                 af[mt][0], af[mt][1], af[mt][2], af[mt][3], b2r, b3r);
                    }
                }
            }
        }
    }

    // ---- epilogue: P (overlays A/B region), combine, store ----
    __syncthreads();
    float* P = reinterpret_cast<float*>(smem + A_OFF);   // [64][260]
    const int fr = lane >> 2, fc = lane & 3;
#pragma unroll
    for (int mt = 0; mt < 2; mt++) {
#pragma unroll
        for (int nt = 0; nt < 8; nt++) {
            const int R0 = m0 + mt * 16 + fr;
            const int C  = n0 + nt * 8 + 2 * fc;
            *reinterpret_cast<float2*>(P + R0 * 260 + C)       = make_float2(d[mt][nt][0], d[mt][nt][1]);
            *reinterpret_cast<float2*>(P + (R0 + 8) * 260 + C) = make_float2(d[mt][nt][2], d[mt][nt][3]);
        }
    }
    __syncthreads();

    {
        const int al = t >> 2, iq = t & 3;
        const float4 ga4 = g4[a0 + al];
        float* orow = out + ((size_t)z * NPTS + a0 + al) * 64;
        const float* Pr = P + al * 260;
#pragma unroll
        for (int u = 0; u < 4; u++) {
            const int i0 = iq * 16 + u * 4;
            const float4 vc = *reinterpret_cast<const float4*>(Pr + i0);
            const float4 v1 = *reinterpret_cast<const float4*>(Pr + 64 + i0);
            const float4 v2 = *reinterpret_cast<const float4*>(Pr + 128 + i0);
            const float4 v3 = *reinterpret_cast<const float4*>(Pr + 192 + i0);
            float4 o;
            o.x = fmaf(-ga4.z, v3.x, fmaf(-ga4.y, v2.x, fmaf(-ga4.x, v1.x, vc.x)));
            o.y = fmaf(-ga4.z, v3.y, fmaf(-ga4.y, v2.y, fmaf(-ga4.x, v1.y, vc.y)));
            o.z = fmaf(-ga4.z, v3.z, fmaf(-ga4.y, v2.z, fmaf(-ga4.x, v1.z, vc.z)));
            o.w = fmaf(-ga4.z, v3.w, fmaf(-ga4.y, v2.w, fmaf(-ga4.x, v1.w, vc.w)));
            *reinterpret_cast<float4*>(orow + i0) = o;
        }
    }
}

// ---------------------------------------------------------------------------
// Launcher. Inputs: features [8,2048,64] f32, geometry [8,2048,3] f32,
// Wk [3,64,64] f32. Output [8,2048,64] f32.
// ---------------------------------------------------------------------------
extern "C" void kernel_launch(void* const* d_in, const int* in_sizes, int n_in,
                              void* d_out, int out_size) {
    const float* feat = (const float*)d_in[0];
    const float* geom = (const float*)d_in[1];
    const float* Wk   = (const float*)d_in[2];
    float* out = (float*)d_out;
    (void)in_sizes; (void)n_in; (void)out_size;

    cudaFuncSetAttribute(prep_kernel,
                         cudaFuncAttributeMaxDynamicSharedMemorySize, SMEM_PREP);
    cudaFuncSetAttribute(conv_mma_kernel,
                         cudaFuncAttributeMaxDynamicSharedMemorySize, SMEM_MAIN);

    prep_kernel<<<dim3(NPTS / 64, BATCH), 256, SMEM_PREP>>>(feat, geom, Wk);
    conv_mma_kernel<<<dim3(NPTS / MT, BATCH), THREADS, SMEM_MAIN>>>(geom, out);
}

// round 14
// speedup vs baseline: 2.1573x; 1.0052x over previous
#include <cuda_runtime.h>
#include <cuda_fp16.h>
#include <cstdint>

#define BATCH 8
#define NPTS  2048
#define CIN   64
#define NIP   256            // H width: [c(64) | e(192)]
#define MT    64             // a-rows per CTA
#define KC    64             // b's per chunk
#define NCHUNK (NPTS / KC)   // 32
#define THREADS 256

// Static device scratch (allocation is forbidden)
__device__ __align__(128) __half g_H[(size_t)BATCH * NIP * NPTS];  // [z][i'][b] fp16

// ---- main-kernel smem layout (bytes) ----
#define GEOM_OFF 0u                  // 2048 x float4 = 32768
#define A_OFF    32768u              // 2 x 8192 (64 rows x 128B, SW128)
#define A_STG    8192u
#define B_OFF    49152u              // 2 x 32768 (256 rows x 128B, SW128)
#define B_STG    32768u
#define SMEM_MAIN (B_OFF + 2u * B_STG)   // 114688 -> 2 CTAs/SM

// ---- prep-kernel smem (floats) ----
#define PWK_F   0
#define PE_F    12288                // E tile 192 x 72
#define PGB_F   26112                // 64 x float4
#define SMEM_PREP ((26112 + 256) * 4)

__device__ __forceinline__ uint32_t smem_u32(const void* p) {
    uint32_t a;
    asm("{ .reg .u64 t; cvta.to.shared.u64 t, %1; cvt.u32.u64 %0, t; }" : "=r"(a) : "l"(p));
    return a;
}
__device__ __forceinline__ void cpasync16(uint32_t dst, const void* src) {
    asm volatile("cp.async.cg.shared.global [%0], [%1], 16;" :: "r"(dst), "l"(src) : "memory");
}
__device__ __forceinline__ void sts32(uint32_t a, uint32_t v) {
    asm volatile("st.shared.b32 [%0], %1;" :: "r"(a), "r"(v) : "memory");
}
__device__ __forceinline__ void ldsm_x4(uint32_t& r0, uint32_t& r1, uint32_t& r2, uint32_t& r3,
                                        uint32_t addr) {
    asm volatile("ldmatrix.sync.aligned.m8n8.x4.shared.b16 {%0,%1,%2,%3}, [%4];"
                 : "=r"(r0), "=r"(r1), "=r"(r2), "=r"(r3) : "r"(addr));
}
__device__ __forceinline__ void mma16816(float& d0, float& d1, float& d2, float& d3,
                                         uint32_t a0, uint32_t a1, uint32_t a2, uint32_t a3,
                                         uint32_t b0, uint32_t b1) {
    asm volatile(
        "mma.sync.aligned.m16n8k16.row.col.f32.f16.f16.f32 "
        "{%0,%1,%2,%3}, {%4,%5,%6,%7}, {%8,%9}, {%0,%1,%2,%3};"
        : "+f"(d0), "+f"(d1), "+f"(d2), "+f"(d3)
        : "r"(a0), "r"(a1), "r"(a2), "r"(a3), "r"(b0), "r"(b1));
}

// ---- packed f32x2 helpers (sm_100+ base ISA; 2x fp32 FMA rate) ----
__device__ __forceinline__ uint64_t pack2(float lo, float hi) {
    uint64_t r;
    asm("mov.b64 %0, {%1, %2};" : "=l"(r) : "f"(lo), "f"(hi));
    return r;
}
__device__ __forceinline__ void unpack2(float& lo, float& hi, uint64_t v) {
    asm("mov.b64 {%0, %1}, %2;" : "=f"(lo), "=f"(hi) : "l"(v));
}
__device__ __forceinline__ uint64_t fma2(uint64_t a, uint64_t b, uint64_t c) {
    uint64_t d;
    asm("fma.rn.f32x2 %0, %1, %2, %3;" : "=l"(d) : "l"(a), "l"(b), "l"(c));
    return d;
}
__device__ __forceinline__ uint64_t mul2(uint64_t a, uint64_t b) {
    uint64_t d;
    asm("mul.rn.f32x2 %0, %1, %2;" : "=l"(d) : "l"(a), "l"(b));
    return d;
}

// ---------------------------------------------------------------------------
// Fused prep (f32x2-packed, bit-identical math to R13): per block (z, b-tile
// of 64): E[192][64] in smem, then H rows (c for r<64, e shifted for r>=64),
// written as fp16 straight to g_H [z][i'][b].
// ---------------------------------------------------------------------------
__global__ __launch_bounds__(256) void prep_kernel(const float* __restrict__ feat,
                                                   const float* __restrict__ geom,
                                                   const float* __restrict__ Wk) {
    extern __shared__ float sp[];
    float* s_wk = sp + PWK_F;
    float* s_E  = sp + PE_F;
    float4* s_gb = reinterpret_cast<float4*>(sp + PGB_F);

    const int z  = blockIdx.y;
    const int b0 = blockIdx.x * 64;
    const int t  = threadIdx.x;

    for (int m = t; m < 3 * 64 * 64 / 4; m += 256)
        reinterpret_cast<float4*>(s_wk)[m] = reinterpret_cast<const float4*>(Wk)[m];
    if (t < 64) {
        const float* gp = geom + ((size_t)z * NPTS + b0 + t) * 3;
        s_gb[t] = make_float4(gp[0], gp[1], gp[2], 0.0f);
    }

    const int bl = t & 63, q = t >> 6;
    ulonglong2 fr[16];   // feature row as packed f32x2 pairs: .x=(f0,f1), .y=(f2,f3)
    const ulonglong2* fp = reinterpret_cast<const ulonglong2*>(
        feat + ((size_t)z * NPTS + b0 + bl) * CIN);
#pragma unroll
    for (int c = 0; c < 16; c++) fr[c] = fp[c];
    __syncthreads();

#pragma unroll 1
    for (int n = 0; n < 48; n++) {
        const int ii = q * 48 + n;
        const ulonglong2* w = reinterpret_cast<const ulonglong2*>(s_wk + ii * 64);
        uint64_t acc01 = 0ull, acc23 = 0ull;   // (a0,a1) and (a2,a3) chains
#pragma unroll
        for (int c = 0; c < 16; c++) {
            const ulonglong2 wv = w[c];
            acc01 = fma2(fr[c].x, wv.x, acc01);
            acc23 = fma2(fr[c].y, wv.y, acc23);
        }
        float a0, a1, a2, a3;
        unpack2(a0, a1, acc01);
        unpack2(a2, a3, acc23);
        s_E[ii * 72 + bl] = (a0 + a1) + (a2 + a3);
    }
    __syncthreads();

    // phase 2: warp w -> rows w*32..; lane l -> b pair (2l, 2l+1), packed f32x2
    const int wrp = t >> 5, l = t & 31;
    const float4 gbA = s_gb[2 * l];
    const float4 gbB = s_gb[2 * l + 1];
    const uint64_t gx2 = pack2(gbA.x, gbB.x);
    const uint64_t gy2 = pack2(gbA.y, gbB.y);
    const uint64_t gz2 = pack2(gbA.z, gbB.z);
    uint32_t* Hh = reinterpret_cast<uint32_t*>(g_H);

#pragma unroll 1
    for (int rr = 0; rr < 32; rr++) {
        const int r = wrp * 32 + rr;
        uint64_t v01;
        if (r < 64) {
            const uint64_t e0 = *reinterpret_cast<const uint64_t*>(&s_E[r * 72 + 2 * l]);
            const uint64_t e1 = *reinterpret_cast<const uint64_t*>(&s_E[(64 + r) * 72 + 2 * l]);
            const uint64_t e2 = *reinterpret_cast<const uint64_t*>(&s_E[(128 + r) * 72 + 2 * l]);
            v01 = fma2(gx2, e0, fma2(gy2, e1, mul2(gz2, e2)));
        } else {
            v01 = *reinterpret_cast<const uint64_t*>(&s_E[(r - 64) * 72 + 2 * l]);
        }
        float v0, v1;
        unpack2(v0, v1, v01);
        const __half2 h = __floats2half2_rn(v0, v1);   // v0 -> low, v1 -> high
        const size_t idx = (((size_t)z * NIP + r) * NPTS + b0) / 2 + l;
        Hh[idx] = *reinterpret_cast<const uint32_t*>(&h);
    }
}

// issue one chunk's B copies (256 rows x 128B, SW128-swizzled)
__device__ __forceinline__ void issue_b_copies(uint32_t bst, int z, int b0, int t) {
#pragma unroll
    for (int it = 0; it < 8; it++) {
        const int m = t + THREADS * it;          // 0..2047
        const int row = m >> 3, c16 = m & 7;
        const uint32_t dst = bst + (uint32_t)row * 128u
                           + (uint32_t)((c16 ^ (row & 7)) << 4);
        const __half* src = g_H + (((size_t)z * NIP + row) * NPTS + b0 + c16 * 8);
        cpasync16(dst, src);
    }
}

// ---------------------------------------------------------------------------
// Main (verbatim R13): per CTA (z, 64 a-rows): P[64 x 256] = M @ H
// (fp16 HMMA, fp32 accum). 8 warps, warp tile 32x64, one syncthreads per
// chunk, double-buffered B, in-CTA mask tile A from whole-z smem geometry.
// Per-chunk order: maskgen -> wait B(j) -> sync -> issue B(j+1) -> MMA.
// ---------------------------------------------------------------------------
__global__ __launch_bounds__(THREADS, 2) void conv_mma_kernel(
    const float* __restrict__ geom, float* __restrict__ out)
{
    extern __shared__ __align__(16) char smem[];
    const uint32_t su = smem_u32(smem);
    float4* g4 = reinterpret_cast<float4*>(smem);

    const int z  = blockIdx.y;
    const int a0 = blockIdx.x * MT;
    const int t  = threadIdx.x;
    const int wid = t >> 5, lane = t & 31;
    const int m0 = (wid >> 2) * 32, n0 = (wid & 3) * 64;

    const float* gz = geom + (size_t)z * NPTS * 3;

    // prologue: chunk-0 B copies + stage whole-z geometry as float4
    issue_b_copies(su + B_OFF, z, 0, t);
    asm volatile("cp.async.commit_group;" ::: "memory");
    {
        float* gf = reinterpret_cast<float*>(smem);
        for (int idx = t; idx < NPTS * 3; idx += THREADS)
            gf[(idx / 3) * 4 + (idx % 3)] = gz[idx];
    }
    __syncthreads();

    // maskgen consts: thread t -> row rg (0..63), k-quarter sg
    const int rg = t >> 2, sg = t & 3;
    const float4 ga = g4[a0 + rg];
    const uint32_t aw_base = su + A_OFF + (uint32_t)rg * 128u;
    const uint32_t rx = (uint32_t)(rg & 7);

    // ldsm lane bases
    const int rowA = m0 + ((lane >> 3) & 1) * 8 + (lane & 7);
    const uint32_t sA = (uint32_t)(lane >> 4), rxA = (uint32_t)(rowA & 7);
    const int rowB = n0 + ((lane >> 4) & 1) * 8 + (lane & 7);
    const uint32_t sB = (uint32_t)((lane >> 3) & 1), rxB = (uint32_t)(rowB & 7);

    float d[2][8][4];
#pragma unroll
    for (int mt = 0; mt < 2; mt++)
#pragma unroll
        for (int nt = 0; nt < 8; nt++)
#pragma unroll
            for (int r = 0; r < 4; r++) d[mt][nt][r] = 0.0f;

#pragma unroll 1
    for (int i = 0; i < NCHUNK; i++) {
        const uint32_t p = (uint32_t)(i & 1);
        const int b0 = i * KC;

        // ---- mask tile A[64 x 64] fp16 (SW128), diff-form norm test ----
        {
            const uint32_t ast = aw_base + p * A_STG;
#pragma unroll
            for (int v = 0; v < 8; v++) {
                const int veff = (v + sg) & 7;
                const int k0 = sg * 16 + 2 * veff;
                const float4 q0 = g4[b0 + k0];
                const float4 q1 = g4[b0 + k0 + 1];
                const float dx0 = q0.x - ga.x, dy0 = q0.y - ga.y, dz0 = q0.z - ga.z;
                const float dx1 = q1.x - ga.x, dy1 = q1.y - ga.y, dz1 = q1.z - ga.z;
                const float nn0 = fmaf(dx0, dx0, fmaf(dy0, dy0, dz0 * dz0));
                const float nn1 = fmaf(dx1, dx1, fmaf(dy1, dy1, dz1 * dz1));
                const uint32_t val = (nn0 < 1.0f ? 0x3C00u : 0u)
                                   | (nn1 < 1.0f ? 0x3C000000u : 0u);
                const uint32_t bc = (uint32_t)(2 * k0);
                sts32(ast + (((bc >> 4) ^ rx) << 4) + (bc & 15u), val);
            }
        }

        asm volatile("cp.async.wait_group 0;" ::: "memory");   // B(j) complete
        __syncthreads();   // A(p)+B(p) visible; all warps done with stage p^1

        if (i + 1 < NCHUNK) {
            issue_b_copies(su + B_OFF + (p ^ 1u) * B_STG, z, b0 + KC, t);
            asm volatile("cp.async.commit_group;" ::: "memory");
        }

        // ---- ldmatrix + 64 HMMA per warp ----
        {
            const uint32_t Ast = su + A_OFF + p * A_STG;
            const uint32_t Bst = su + B_OFF + p * B_STG;
#pragma unroll
            for (int kk = 0; kk < 4; kk++) {
                uint32_t af[2][4];
#pragma unroll
                for (int mt = 0; mt < 2; mt++)
                    ldsm_x4(af[mt][0], af[mt][1], af[mt][2], af[mt][3],
                            Ast + (uint32_t)(rowA + mt * 16) * 128u
                                + ((((uint32_t)kk * 2u + sA) ^ rxA) << 4));
#pragma unroll
                for (int ntp = 0; ntp < 4; ntp++) {
                    uint32_t b0r, b1r, b2r, b3r;
                    ldsm_x4(b0r, b1r, b2r, b3r,
                            Bst + (uint32_t)(rowB + ntp * 16) * 128u
                               + ((((uint32_t)kk * 2u + sB) ^ rxB) << 4));
#pragma unroll
                    for (int mt = 0; mt < 2; mt++) {
                        mma16816(d[mt][2*ntp][0], d[mt][2*ntp][1], d[mt][2*ntp][2], d[mt][2*ntp][3],
                                 af[mt][0], af[mt][1], af[mt][2], af[mt][3], b0r, b1r);
                        mma16816(d[mt][2*ntp+1][0], d[mt][2*ntp+1][1], d[mt][2*ntp+1][2], d[mt][2*ntp+1][3],
                                 af[mt][0], af[mt][1], af[mt][2], af[mt][3], b2r, b3r);
                    }
                }
            }
        }
    }

    // ---- epilogue: P (overlays A/B region), combine, store ----
    __syncthreads();
    float* P = reinterpret_cast<float*>(smem + A_OFF);   // [64][260]
    const int fr = lane >> 2, fc = lane & 3;
#pragma unroll
    for (int mt = 0; mt < 2; mt++) {
#pragma unroll
        for (int nt = 0; nt < 8; nt++) {
            const int R0 = m0 + mt * 16 + fr;
            const int C  = n0 + nt * 8 + 2 * fc;
            *reinterpret_cast<float2*>(P + R0 * 260 + C)       = make_float2(d[mt][nt][0], d[mt][nt][1]);
            *reinterpret_cast<float2*>(P + (R0 + 8) * 260 + C) = make_float2(d[mt][nt][2], d[mt][nt][3]);
        }
    }
    __syncthreads();

    {
        const int al = t >> 2, iq = t & 3;
        const float4 ga4 = g4[a0 + al];
        float* orow = out + ((size_t)z * NPTS + a0 + al) * 64;
        const float* Pr = P + al * 260;
#pragma unroll
        for (int u = 0; u < 4; u++) {
            const int i0 = iq * 16 + u * 4;
            const float4 vc = *reinterpret_cast<const float4*>(Pr + i0);
            const float4 v1 = *reinterpret_cast<const float4*>(Pr + 64 + i0);
            const float4 v2 = *reinterpret_cast<const float4*>(Pr + 128 + i0);
            const float4 v3 = *reinterpret_cast<const float4*>(Pr + 192 + i0);
            float4 o;
            o.x = fmaf(-ga4.z, v3.x, fmaf(-ga4.y, v2.x, fmaf(-ga4.x, v1.x, vc.x)));
            o.y = fmaf(-ga4.z, v3.y, fmaf(-ga4.y, v2.y, fmaf(-ga4.x, v1.y, vc.y)));
            o.z = fmaf(-ga4.z, v3.z, fmaf(-ga4.y, v2.z, fmaf(-ga4.x, v1.z, vc.z)));
            o.w = fmaf(-ga4.z, v3.w, fmaf(-ga4.y, v2.w, fmaf(-ga4.x, v1.w, vc.w)));
            *reinterpret_cast<float4*>(orow + i0) = o;
        }
    }
}

// ---------------------------------------------------------------------------
// Launcher. Inputs: features [8,2048,64] f32, geometry [8,2048,3] f32,
// Wk [3,64,64] f32. Output [8,2048,64] f32.
// ---------------------------------------------------------------------------
extern "C" void kernel_launch(void* const* d_in, const int* in_sizes, int n_in,
                              void* d_out, int out_size) {
    const float* feat = (const float*)d_in[0];
    const float* geom = (const float*)d_in[1];
    const float* Wk   = (const float*)d_in[2];
    float* out = (float*)d_out;
    (void)in_sizes; (void)n_in; (void)out_size;

    cudaFuncSetAttribute(prep_kernel,
                         cudaFuncAttributeMaxDynamicSharedMemorySize, SMEM_PREP);
    cudaFuncSetAttribute(conv_mma_kernel,
                         cudaFuncAttributeMaxDynamicSharedMemorySize, SMEM_MAIN);

    prep_kernel<<<dim3(NPTS / 64, BATCH), 256, SMEM_PREP>>>(feat, geom, Wk);
    conv_mma_kernel<<<dim3(NPTS / MT, BATCH), THREADS, SMEM_MAIN>>>(geom, out);
}

// round 15
// speedup vs baseline: 2.1679x; 1.0049x over previous
#include <cuda_runtime.h>
#include <cuda_fp16.h>
#include <cstdint>

#define BATCH 8
#define NPTS  2048
#define CIN   64
#define NIP   256            // H width: [c(64) | e(192)]
#define MT    64             // a-rows per CTA == b-tile size
#define KC    64             // b's per chunk
#define NCHUNK (NPTS / KC)   // 32
#define THREADS 256
#define NCTAS  (BATCH * NCHUNK)   // 256 total CTAs (all co-resident at 2/SM)

// Static device scratch (allocation is forbidden)
__device__ __align__(128) __half g_H[(size_t)BATCH * NIP * NPTS];  // [z][i'][b] fp16
__device__ int g_bar;   // device-wide barrier counter (memset to 0 per launch)

// ---- main-kernel smem layout (bytes) ----
#define GEOM_OFF 0u                  // 2048 x float4 = 32768
#define A_OFF    32768u              // 2 x 8192 (64 rows x 128B, SW128)
#define A_STG    8192u
#define B_OFF    49152u              // 2 x 32768 (256 rows x 128B, SW128)
#define B_STG    32768u
#define SMEM_MAIN (B_OFF + 2u * B_STG)   // 114688 -> 2 CTAs/SM
// phase A reuses bytes [B_OFF, B_OFF+48KB) as Wk scratch before the GEMM

__device__ __forceinline__ uint32_t smem_u32(const void* p) {
    uint32_t a;
    asm("{ .reg .u64 t; cvta.to.shared.u64 t, %1; cvt.u32.u64 %0, t; }" : "=r"(a) : "l"(p));
    return a;
}
__device__ __forceinline__ void cpasync16(uint32_t dst, const void* src) {
    asm volatile("cp.async.cg.shared.global [%0], [%1], 16;" :: "r"(dst), "l"(src) : "memory");
}
__device__ __forceinline__ void sts32(uint32_t a, uint32_t v) {
    asm volatile("st.shared.b32 [%0], %1;" :: "r"(a), "r"(v) : "memory");
}
__device__ __forceinline__ void ldsm_x4(uint32_t& r0, uint32_t& r1, uint32_t& r2, uint32_t& r3,
                                        uint32_t addr) {
    asm volatile("ldmatrix.sync.aligned.m8n8.x4.shared.b16 {%0,%1,%2,%3}, [%4];"
                 : "=r"(r0), "=r"(r1), "=r"(r2), "=r"(r3) : "r"(addr));
}
__device__ __forceinline__ void mma16816(float& d0, float& d1, float& d2, float& d3,
                                         uint32_t a0, uint32_t a1, uint32_t a2, uint32_t a3,
                                         uint32_t b0, uint32_t b1) {
    asm volatile(
        "mma.sync.aligned.m16n8k16.row.col.f32.f16.f16.f32 "
        "{%0,%1,%2,%3}, {%4,%5,%6,%7}, {%8,%9}, {%0,%1,%2,%3};"
        : "+f"(d0), "+f"(d1), "+f"(d2), "+f"(d3)
        : "r"(a0), "r"(a1), "r"(a2), "r"(a3), "r"(b0), "r"(b1));
}

// ---- packed f32x2 helpers (sm_100+ base ISA) ----
__device__ __forceinline__ void unpack2(float& lo, float& hi, uint64_t v) {
    asm("mov.b64 {%0, %1}, %2;" : "=f"(lo), "=f"(hi) : "l"(v));
}
__device__ __forceinline__ uint64_t fma2(uint64_t a, uint64_t b, uint64_t c) {
    uint64_t d;
    asm("fma.rn.f32x2 %0, %1, %2, %3;" : "=l"(d) : "l"(a), "l"(b), "l"(c));
    return d;
}

// issue one chunk's B copies (256 rows x 128B, SW128-swizzled)
__device__ __forceinline__ void issue_b_copies(uint32_t bst, int z, int b0, int t) {
#pragma unroll
    for (int it = 0; it < 8; it++) {
        const int m = t + THREADS * it;          // 0..2047
        const int row = m >> 3, c16 = m & 7;
        const uint32_t dst = bst + (uint32_t)row * 128u
                           + (uint32_t)((c16 ^ (row & 7)) << 4);
        const __half* src = g_H + (((size_t)z * NIP + row) * NPTS + b0 + c16 * 8);
        cpasync16(dst, src);
    }
}

// ---------------------------------------------------------------------------
// Fused kernel.
// Phase A: this CTA produces H[z][*][b-tile bx] (c rows + e rows, fp16) with
//   the same FP chains as the R14 prep (bit-identical output).
// Device barrier: all 256 CTAs co-resident (2/SM, enforced by launch_bounds);
//   threadfence + atomicAdd + spin.
// Phase B: verbatim R13/R14 GEMM: P[64 x 256] = M @ H, fp16 HMMA, 8 warps,
//   warp tile 32x64, 1 sync/chunk, double-buffered B, in-CTA mask tile.
// ---------------------------------------------------------------------------
__global__ __launch_bounds__(THREADS, 2) void conv_fused_kernel(
    const float* __restrict__ feat,
    const float* __restrict__ geom,
    const float* __restrict__ Wk,
    float* __restrict__ out)
{
    extern __shared__ __align__(16) char smem[];
    const uint32_t su = smem_u32(smem);
    float4* g4 = reinterpret_cast<float4*>(smem);

    const int z  = blockIdx.y;
    const int a0 = blockIdx.x * MT;      // also this CTA's b-tile base
    const int t  = threadIdx.x;
    const int wid = t >> 5, lane = t & 31;
    const int m0 = (wid >> 2) * 32, n0 = (wid & 3) * 64;

    const float* gz = geom + (size_t)z * NPTS * 3;

    // ---- stage whole-z geometry as float4 (needed by phase A and maskgen) ----
    {
        float* gf = reinterpret_cast<float*>(smem);
        for (int idx = t; idx < NPTS * 3; idx += THREADS)
            gf[(idx / 3) * 4 + (idx % 3)] = gz[idx];
    }

    // ---- phase A: produce H[z][*][a0..a0+63] ----
    {
        float* s_wk = reinterpret_cast<float*>(smem + B_OFF);   // 48KB scratch
        for (int m = t; m < 3 * 64 * 64 / 4; m += 256)
            reinterpret_cast<float4*>(s_wk)[m] = reinterpret_cast<const float4*>(Wk)[m];

        const int bl = t & 63, q = t >> 6;
        const int bg = a0 + bl;
        ulonglong2 fr[16];   // feature row, packed f32x2 pairs
        const ulonglong2* fp = reinterpret_cast<const ulonglong2*>(
            feat + ((size_t)z * NPTS + bg) * CIN);
#pragma unroll
        for (int c = 0; c < 16; c++) fr[c] = fp[c];
        __syncthreads();   // wk + geometry staged

        const float4 gb = g4[bg];
        __half* Hp = g_H;

#pragma unroll 1
        for (int n = 0; n < 16; n++) {
            const int i = q * 16 + n;
            float Ex0, Ex1, Ex2;
#pragma unroll
            for (int x = 0; x < 3; x++) {
                const ulonglong2* w = reinterpret_cast<const ulonglong2*>(
                    s_wk + (x * 64 + i) * 64);
                uint64_t acc01 = 0ull, acc23 = 0ull;
#pragma unroll
                for (int c = 0; c < 16; c++) {
                    acc01 = fma2(fr[c].x, w[c].x, acc01);
                    acc23 = fma2(fr[c].y, w[c].y, acc23);
                }
                float e0, e1, e2, e3;
                unpack2(e0, e1, acc01);
                unpack2(e2, e3, acc23);
                const float E = (e0 + e1) + (e2 + e3);
                if (x == 0) Ex0 = E; else if (x == 1) Ex1 = E; else Ex2 = E;
                Hp[((size_t)z * NIP + 64 + 64 * x + i) * NPTS + bg] = __float2half_rn(E);
            }
            const float cv = fmaf(gb.x, Ex0, fmaf(gb.y, Ex1, gb.z * Ex2));
            Hp[((size_t)z * NIP + i) * NPTS + bg] = __float2half_rn(cv);
        }
    }

    // ---- device-wide barrier (all 256 CTAs co-resident) ----
    __threadfence();          // make this thread's H stores device-visible
    __syncthreads();
    if (t == 0) {
        atomicAdd(&g_bar, 1);
        while (*reinterpret_cast<volatile int*>(&g_bar) < NCTAS) {}
        __threadfence();
    }
    __syncthreads();

    // ---- phase B prologue: chunk-0 B copies ----
    issue_b_copies(su + B_OFF, z, 0, t);
    asm volatile("cp.async.commit_group;" ::: "memory");

    // maskgen consts: thread t -> row rg (0..63), k-quarter sg
    const int rg = t >> 2, sg = t & 3;
    const float4 ga = g4[a0 + rg];
    const uint32_t aw_base = su + A_OFF + (uint32_t)rg * 128u;
    const uint32_t rx = (uint32_t)(rg & 7);

    // ldsm lane bases
    const int rowA = m0 + ((lane >> 3) & 1) * 8 + (lane & 7);
    const uint32_t sA = (uint32_t)(lane >> 4), rxA = (uint32_t)(rowA & 7);
    const int rowB = n0 + ((lane >> 4) & 1) * 8 + (lane & 7);
    const uint32_t sB = (uint32_t)((lane >> 3) & 1), rxB = (uint32_t)(rowB & 7);

    float d[2][8][4];
#pragma unroll
    for (int mt = 0; mt < 2; mt++)
#pragma unroll
        for (int nt = 0; nt < 8; nt++)
#pragma unroll
            for (int r = 0; r < 4; r++) d[mt][nt][r] = 0.0f;

#pragma unroll 1
    for (int i = 0; i < NCHUNK; i++) {
        const uint32_t p = (uint32_t)(i & 1);
        const int b0 = i * KC;

        // ---- mask tile A[64 x 64] fp16 (SW128), diff-form norm test ----
        {
            const uint32_t ast = aw_base + p * A_STG;
#pragma unroll
            for (int v = 0; v < 8; v++) {
                const int veff = (v + sg) & 7;
                const int k0 = sg * 16 + 2 * veff;
                const float4 q0 = g4[b0 + k0];
                const float4 q1 = g4[b0 + k0 + 1];
                const float dx0 = q0.x - ga.x, dy0 = q0.y - ga.y, dz0 = q0.z - ga.z;
                const float dx1 = q1.x - ga.x, dy1 = q1.y - ga.y, dz1 = q1.z - ga.z;
                const float nn0 = fmaf(dx0, dx0, fmaf(dy0, dy0, dz0 * dz0));
                const float nn1 = fmaf(dx1, dx1, fmaf(dy1, dy1, dz1 * dz1));
                const uint32_t val = (nn0 < 1.0f ? 0x3C00u : 0u)
                                   | (nn1 < 1.0f ? 0x3C000000u : 0u);
                const uint32_t bc = (uint32_t)(2 * k0);
                sts32(ast + (((bc >> 4) ^ rx) << 4) + (bc & 15u), val);
            }
        }

        asm volatile("cp.async.wait_group 0;" ::: "memory");   // B(j) complete
        __syncthreads();   // A(p)+B(p) visible; all warps done with stage p^1

        if (i + 1 < NCHUNK) {
            issue_b_copies(su + B_OFF + (p ^ 1u) * B_STG, z, b0 + KC, t);
            asm volatile("cp.async.commit_group;" ::: "memory");
        }

        // ---- ldmatrix + 64 HMMA per warp ----
        {
            const uint32_t Ast = su + A_OFF + p * A_STG;
            const uint32_t Bst = su + B_OFF + p * B_STG;
#pragma unroll
            for (int kk = 0; kk < 4; kk++) {
                uint32_t af[2][4];
#pragma unroll
                for (int mt = 0; mt < 2; mt++)
                    ldsm_x4(af[mt][0], af[mt][1], af[mt][2], af[mt][3],
                            Ast + (uint32_t)(rowA + mt * 16) * 128u
                                + ((((uint32_t)kk * 2u + sA) ^ rxA) << 4));
#pragma unroll
                for (int ntp = 0; ntp < 4; ntp++) {
                    uint32_t b0r, b1r, b2r, b3r;
                    ldsm_x4(b0r, b1r, b2r, b3r,
                            Bst + (uint32_t)(rowB + ntp * 16) * 128u
                               + ((((uint32_t)kk * 2u + sB) ^ rxB) << 4));
#pragma unroll
                    for (int mt = 0; mt < 2; mt++) {
                        mma16816(d[mt][2*ntp][0], d[mt][2*ntp][1], d[mt][2*ntp][2], d[mt][2*ntp][3],
                                 af[mt][0], af[mt][1], af[mt][2], af[mt][3], b0r, b1r);
                        mma16816(d[mt][2*ntp+1][0], d[mt][2*ntp+1][1], d[mt][2*ntp+1][2], d[mt][2*ntp+1][3],
                                 af[mt][0], af[mt][1], af[mt][2], af[mt][3], b2r, b3r);
                    }
                }
            }
        }
    }

    // ---- epilogue: P (overlays A/B region), combine, store ----
    __syncthreads();
    float* P = reinterpret_cast<float*>(smem + A_OFF);   // [64][260]
    const int fr = lane >> 2, fc = lane & 3;
#pragma unroll
    for (int mt = 0; mt < 2; mt++) {
#pragma unroll
        for (int nt = 0; nt < 8; nt++) {
            const int R0 = m0 + mt * 16 + fr;
            const int C  = n0 + nt * 8 + 2 * fc;
            *reinterpret_cast<float2*>(P + R0 * 260 + C)       = make_float2(d[mt][nt][0], d[mt][nt][1]);
            *reinterpret_cast<float2*>(P + (R0 + 8) * 260 + C) = make_float2(d[mt][nt][2], d[mt][nt][3]);
        }
    }
    __syncthreads();

    {
        const int al = t >> 2, iq = t & 3;
        const float4 ga4 = g4[a0 + al];
        float* orow = out + ((size_t)z * NPTS + a0 + al) * 64;
        const float* Pr = P + al * 260;
#pragma unroll
        for (int u = 0; u < 4; u++) {
            const int i0 = iq * 16 + u * 4;
            const float4 vc = *reinterpret_cast<const float4*>(Pr + i0);
            const float4 v1 = *reinterpret_cast<const float4*>(Pr + 64 + i0);
            const float4 v2 = *reinterpret_cast<const float4*>(Pr + 128 + i0);
            const float4 v3 = *reinterpret_cast<const float4*>(Pr + 192 + i0);
            float4 o;
            o.x = fmaf(-ga4.z, v3.x, fmaf(-ga4.y, v2.x, fmaf(-ga4.x, v1.x, vc.x)));
            o.y = fmaf(-ga4.z, v3.y, fmaf(-ga4.y, v2.y, fmaf(-ga4.x, v1.y, vc.y)));
            o.z = fmaf(-ga4.z, v3.z, fmaf(-ga4.y, v2.z, fmaf(-ga4.x, v1.z, vc.z)));
            o.w = fmaf(-ga4.z, v3.w, fmaf(-ga4.y, v2.w, fmaf(-ga4.x, v1.w, vc.w)));
            *reinterpret_cast<float4*>(orow + i0) = o;
        }
    }
}

// ---------------------------------------------------------------------------
// Launcher. Inputs: features [8,2048,64] f32, geometry [8,2048,3] f32,
// Wk [3,64,64] f32. Output [8,2048,64] f32.
// Single compute launch; g_bar zeroed via graph-capturable memset.
// ---------------------------------------------------------------------------
extern "C" void kernel_launch(void* const* d_in, const int* in_sizes, int n_in,
                              void* d_out, int out_size) {
    const float* feat = (const float*)d_in[0];
    const float* geom = (const float*)d_in[1];
    const float* Wk   = (const float*)d_in[2];
    float* out = (float*)d_out;
    (void)in_sizes; (void)n_in; (void)out_size;

    void* bar_ptr = nullptr;
    cudaGetSymbolAddress(&bar_ptr, g_bar);
    cudaMemsetAsync(bar_ptr, 0, sizeof(int), 0);

    cudaFuncSetAttribute(conv_fused_kernel,
                         cudaFuncAttributeMaxDynamicSharedMemorySize, SMEM_MAIN);
    conv_fused_kernel<<<dim3(NPTS / MT, BATCH), THREADS, SMEM_MAIN>>>(
        feat, geom, Wk, out);
}